// round 1
// baseline (speedup 1.0000x reference)
#include <cuda_runtime.h>
#include <math.h>

#define NTOK 4096
#define DDIM 512
#define IDIM 2048
#define NEXP 8
#define MAXTILES 40   // sum_e ceil(cnt_e/128) <= 4096/128 + 8 = 40

// ---------------- device scratch (no allocations allowed) ----------------
__device__ float g_H[(size_t)NTOK * IDIM];   // 33.5 MB: gelu(x@sw1^T), later silu(a1)*a3
__device__ float g_A1[(size_t)NTOK * IDIM];  // 33.5 MB: x@w1^T (pre-silu)
__device__ int g_expert[NTOK];
__device__ int g_pos[NTOK];
__device__ int g_perm[NTOK];    // sorted position -> token id
__device__ int g_cnt[NEXP];
__device__ int g_off[NEXP];
__device__ int g_tileE[64];
__device__ int g_tileRow[64];
__device__ int g_tileCnt[64];
__device__ int g_numTiles;

// ---------------- small kernels ----------------
__global__ void zero_kernel() {
    if (threadIdx.x < NEXP) g_cnt[threadIdx.x] = 0;
}

// One warp per token: logits = x @ gate_w^T, argmax (K=1 => weight==1).
__global__ void gate_kernel(const float* __restrict__ x, const float* __restrict__ gw) {
    int warp = (int)((blockIdx.x * blockDim.x + threadIdx.x) >> 5);
    int lane = threadIdx.x & 31;
    if (warp >= NTOK) return;
    const float4* xr = reinterpret_cast<const float4*>(x + (size_t)warp * DDIM + lane * 16);
    float4 xv[4];
#pragma unroll
    for (int j = 0; j < 4; j++) xv[j] = xr[j];
    float best = -1e30f; int bi = 0;
#pragma unroll
    for (int e = 0; e < NEXP; e++) {
        const float4* gr = reinterpret_cast<const float4*>(gw + (size_t)e * DDIM + lane * 16);
        float s = 0.f;
#pragma unroll
        for (int j = 0; j < 4; j++) {
            float4 g = gr[j];
            s += xv[j].x * g.x + xv[j].y * g.y + xv[j].z * g.z + xv[j].w * g.w;
        }
#pragma unroll
        for (int o = 16; o > 0; o >>= 1) s += __shfl_xor_sync(0xffffffffu, s, o);
        if (s > best) { best = s; bi = e; }   // strict > : lowest index wins ties (matches top_k)
    }
    if (lane == 0) {
        g_expert[warp] = bi;
        g_pos[warp] = atomicAdd(&g_cnt[bi], 1);
    }
}

// Single thread: exclusive scan + per-expert 128-row tile table.
__global__ void build_tiles_kernel() {
    int off = 0;
    for (int e = 0; e < NEXP; e++) { g_off[e] = off; off += g_cnt[e]; }
    int nt = 0;
    for (int e = 0; e < NEXP; e++) {
        for (int r = 0; r < g_cnt[e]; r += 128) {
            g_tileE[nt] = e;
            g_tileRow[nt] = g_off[e] + r;
            g_tileCnt[nt] = min(128, g_cnt[e] - r);
            nt++;
        }
    }
    g_numTiles = nt;
}

__global__ void scatter_kernel() {
    int t = blockIdx.x * blockDim.x + threadIdx.x;
    if (t >= NTOK) return;
    int sp = g_off[g_expert[t]] + g_pos[t];
    g_perm[sp] = t;
}

// ---------------- epilogue helpers ----------------
__device__ __forceinline__ float gelu_exact(float v) {
    return 0.5f * v * (1.0f + erff(v * 0.70710678118654752f));
}
__device__ __forceinline__ float silu_f(float v) {
    return v / (1.0f + expf(-v));
}

// ---------------- 128x128x8 SGEMM (fp32), epilogue by MODE ----------------
// MODE 0: Hs  = gelu(x @ sw1^T)              A=x (identity rows), C=g_H
// MODE 1: out = Hs @ sw2^T                   A=g_H (identity rows), C=out (=)
// MODE 2: A1  = Xg @ w1[e]^T                 A=x gathered via perm, C=g_A1 (by sorted pos)
// MODE 3: H   = silu(A1) * (Xg @ w3[e]^T)    A=x gathered, C=g_H (by sorted pos)
// MODE 4: out[perm[sp]] += H @ w2[e]^T       A=g_H (sorted pos rows), scatter-add
template<int MODE>
__global__ __launch_bounds__(256, 2)
void gemm128(const float* __restrict__ Aext,
             const float* __restrict__ Bglob,
             float* __restrict__ Dout,
             int Kdim, long bStride)
{
    __shared__ float As[8][132];
    __shared__ float Bs[8][132];

    int bx = blockIdx.x, by = blockIdx.y;
    int rowStart, rowCnt, eid;
    if (MODE == 0 || MODE == 1) {
        rowStart = bx * 128; rowCnt = 128; eid = 0;
    } else {
        if (bx >= g_numTiles) return;
        eid = g_tileE[bx]; rowStart = g_tileRow[bx]; rowCnt = g_tileCnt[bx];
    }

    const float* Abase = (MODE == 1 || MODE == 4) ? g_H : Aext;
    const float* Bptr  = Bglob + (long)eid * bStride;

    int tid = threadIdx.x;
    int m_l = tid >> 1;           // 0..127 (loader row / col)
    int k4  = (tid & 1) * 4;      // 0 or 4

    const float* aRow = nullptr;
    if (m_l < rowCnt) {
        int r = rowStart + m_l;
        int arow = (MODE == 2 || MODE == 3) ? g_perm[r] : r;
        aRow = Abase + (size_t)arow * Kdim;
    }
    int nCol = by * 128 + m_l;
    const float* bRow = Bptr + (size_t)nCol * Kdim;

    int tx = tid & 15, ty = tid >> 4;
    float acc[8][8];
#pragma unroll
    for (int i = 0; i < 8; i++)
#pragma unroll
        for (int j = 0; j < 8; j++) acc[i][j] = 0.f;

    for (int kk = 0; kk < Kdim; kk += 8) {
        float4 av = aRow ? *reinterpret_cast<const float4*>(aRow + kk + k4)
                         : make_float4(0.f, 0.f, 0.f, 0.f);
        float4 bv = *reinterpret_cast<const float4*>(bRow + kk + k4);
        As[k4 + 0][m_l] = av.x; As[k4 + 1][m_l] = av.y;
        As[k4 + 2][m_l] = av.z; As[k4 + 3][m_l] = av.w;
        Bs[k4 + 0][m_l] = bv.x; Bs[k4 + 1][m_l] = bv.y;
        Bs[k4 + 2][m_l] = bv.z; Bs[k4 + 3][m_l] = bv.w;
        __syncthreads();
#pragma unroll
        for (int k = 0; k < 8; k++) {
            float4 a0 = *reinterpret_cast<const float4*>(&As[k][ty * 8]);
            float4 a1 = *reinterpret_cast<const float4*>(&As[k][ty * 8 + 4]);
            float4 b0 = *reinterpret_cast<const float4*>(&Bs[k][tx * 8]);
            float4 b1 = *reinterpret_cast<const float4*>(&Bs[k][tx * 8 + 4]);
            float a[8] = {a0.x, a0.y, a0.z, a0.w, a1.x, a1.y, a1.z, a1.w};
            float b[8] = {b0.x, b0.y, b0.z, b0.w, b1.x, b1.y, b1.z, b1.w};
#pragma unroll
            for (int i = 0; i < 8; i++)
#pragma unroll
                for (int j = 0; j < 8; j++) acc[i][j] = fmaf(a[i], b[j], acc[i][j]);
        }
        __syncthreads();
    }

    // epilogue
    int colBase = by * 128 + tx * 8;
#pragma unroll
    for (int i = 0; i < 8; i++) {
        int m = ty * 8 + i;
        if ((MODE >= 2) && m >= rowCnt) continue;
        int sp = rowStart + m;
        if (MODE == 0) {
            float* c = g_H + (size_t)sp * IDIM + colBase;
#pragma unroll
            for (int j = 0; j < 8; j++) c[j] = gelu_exact(acc[i][j]);
        } else if (MODE == 1) {
            float* c = Dout + (size_t)sp * DDIM + colBase;
            float4 v0 = make_float4(acc[i][0], acc[i][1], acc[i][2], acc[i][3]);
            float4 v1 = make_float4(acc[i][4], acc[i][5], acc[i][6], acc[i][7]);
            reinterpret_cast<float4*>(c)[0] = v0;
            reinterpret_cast<float4*>(c)[1] = v1;
        } else if (MODE == 2) {
            float* c = g_A1 + (size_t)sp * IDIM + colBase;
            float4 v0 = make_float4(acc[i][0], acc[i][1], acc[i][2], acc[i][3]);
            float4 v1 = make_float4(acc[i][4], acc[i][5], acc[i][6], acc[i][7]);
            reinterpret_cast<float4*>(c)[0] = v0;
            reinterpret_cast<float4*>(c)[1] = v1;
        } else if (MODE == 3) {
            const float* a1p = g_A1 + (size_t)sp * IDIM + colBase;
            float* c = g_H + (size_t)sp * IDIM + colBase;
#pragma unroll
            for (int j = 0; j < 8; j++) c[j] = silu_f(a1p[j]) * acc[i][j];
        } else { // MODE == 4: scatter-add into out
            int tok = g_perm[sp];
            float* c = Dout + (size_t)tok * DDIM + colBase;
            float4 o0 = reinterpret_cast<float4*>(c)[0];
            float4 o1 = reinterpret_cast<float4*>(c)[1];
            o0.x += acc[i][0]; o0.y += acc[i][1]; o0.z += acc[i][2]; o0.w += acc[i][3];
            o1.x += acc[i][4]; o1.y += acc[i][5]; o1.z += acc[i][6]; o1.w += acc[i][7];
            reinterpret_cast<float4*>(c)[0] = o0;
            reinterpret_cast<float4*>(c)[1] = o1;
        }
    }
}

// ---------------- launch ----------------
extern "C" void kernel_launch(void* const* d_in, const int* in_sizes, int n_in,
                              void* d_out, int out_size) {
    const float* x   = (const float*)d_in[0];   // [4096, 512]
    const float* gw  = (const float*)d_in[1];   // [8, 512]
    const float* w1  = (const float*)d_in[2];   // [8, 2048, 512]
    const float* w2  = (const float*)d_in[3];   // [8, 512, 2048]
    const float* w3  = (const float*)d_in[4];   // [8, 2048, 512]
    const float* sw1 = (const float*)d_in[5];   // [2048, 512]
    const float* sw2 = (const float*)d_in[6];   // [512, 2048]
    float* out = (float*)d_out;                 // [4096, 512]

    zero_kernel<<<1, 32>>>();
    gate_kernel<<<NTOK / 8, 256>>>(x, gw);
    build_tiles_kernel<<<1, 1>>>();
    scatter_kernel<<<NTOK / 256, 256>>>();

    // shared expert: out = gelu(x @ sw1^T) @ sw2^T
    gemm128<0><<<dim3(NTOK / 128, IDIM / 128), 256>>>(x, sw1, nullptr, DDIM, 0);
    gemm128<1><<<dim3(NTOK / 128, DDIM / 128), 256>>>(nullptr, sw2, out, IDIM, 0);

    // routed experts (top-1, weight == 1): out[tok] += w2[e] @ (silu(w1[e]x) * (w3[e]x))
    gemm128<2><<<dim3(MAXTILES, IDIM / 128), 256>>>(x, w1, nullptr, DDIM, (long)IDIM * DDIM);
    gemm128<3><<<dim3(MAXTILES, IDIM / 128), 256>>>(x, w3, nullptr, DDIM, (long)IDIM * DDIM);
    gemm128<4><<<dim3(MAXTILES, DDIM / 128), 256>>>(nullptr, w2, out, IDIM, (long)DDIM * IDIM);
}

// round 3
// speedup vs baseline: 2.4623x; 2.4623x over previous
#include <cuda_runtime.h>
#include <cuda_bf16.h>
#include <math.h>
#include <stdint.h>

#define NTOK 4096
#define DDIM 512
#define IDIM 2048
#define NEXP 8
#define MAXTILES 40
#define STG 40960           // bytes per pipeline stage (Ahi,Alo,Bhi,Blo @ 10240 each)
#define SMEMSZ (2 * STG)
#define SA 40               // smem row stride in bf16 elems (80 B)

// ===================== device scratch =====================
__device__ int g_expert[NTOK];
__device__ int g_pos[NTOK];
__device__ int g_perm[NTOK];
__device__ int g_cnt[NEXP];
__device__ int g_off[NEXP];
__device__ int g_tileE[64];
__device__ int g_tileRow[64];
__device__ int g_tileCnt[64];
__device__ int g_numTiles;

__device__ __nv_bfloat16 g_xhi[(size_t)NTOK * DDIM];
__device__ __nv_bfloat16 g_xlo[(size_t)NTOK * DDIM];
__device__ __nv_bfloat16 g_sw1hi[(size_t)IDIM * DDIM];
__device__ __nv_bfloat16 g_sw1lo[(size_t)IDIM * DDIM];
__device__ __nv_bfloat16 g_sw2hi[(size_t)DDIM * IDIM];
__device__ __nv_bfloat16 g_sw2lo[(size_t)DDIM * IDIM];
__device__ __nv_bfloat16 g_w1hi[(size_t)NEXP * IDIM * DDIM];
__device__ __nv_bfloat16 g_w1lo[(size_t)NEXP * IDIM * DDIM];
__device__ __nv_bfloat16 g_w3hi[(size_t)NEXP * IDIM * DDIM];
__device__ __nv_bfloat16 g_w3lo[(size_t)NEXP * IDIM * DDIM];
__device__ __nv_bfloat16 g_w2hi[(size_t)NEXP * DDIM * IDIM];
__device__ __nv_bfloat16 g_w2lo[(size_t)NEXP * DDIM * IDIM];
__device__ __nv_bfloat16 g_Hshi[(size_t)NTOK * IDIM];
__device__ __nv_bfloat16 g_Hslo[(size_t)NTOK * IDIM];
__device__ __nv_bfloat16 g_Hrhi[(size_t)NTOK * IDIM];
__device__ __nv_bfloat16 g_Hrlo[(size_t)NTOK * IDIM];
__device__ float g_A1[(size_t)NTOK * IDIM];

// ===================== PTX helpers =====================
__device__ __forceinline__ uint32_t smem_u32(const void* p) {
    uint32_t a;
    asm("{ .reg .u64 t; cvta.to.shared.u64 t, %1; cvt.u32.u64 %0, t; }" : "=r"(a) : "l"(p));
    return a;
}
#define CP16(dst, src) asm volatile("cp.async.cg.shared.global [%0], [%1], 16;" :: "r"(dst), "l"(src))
#define CP_COMMIT()    asm volatile("cp.async.commit_group;" ::: "memory")
#define CP_WAIT1()     asm volatile("cp.async.wait_group 1;" ::: "memory")
#define CP_WAIT0()     asm volatile("cp.async.wait_group 0;" ::: "memory")

#define LDSM4(r0, r1, r2, r3, a) \
    asm volatile("ldmatrix.sync.aligned.m8n8.x4.shared.b16 {%0,%1,%2,%3}, [%4];" \
        : "=r"(r0), "=r"(r1), "=r"(r2), "=r"(r3) : "r"(a))

#define MMA(d, A, B) \
    asm volatile("mma.sync.aligned.m16n8k16.row.col.f32.bf16.bf16.f32 " \
        "{%0,%1,%2,%3},{%4,%5,%6,%7},{%8,%9},{%0,%1,%2,%3};" \
        : "+f"((d)[0]), "+f"((d)[1]), "+f"((d)[2]), "+f"((d)[3]) \
        : "r"((A)[0]), "r"((A)[1]), "r"((A)[2]), "r"((A)[3]), "r"((B)[0]), "r"((B)[1]))

// ===================== setup kernels =====================
__global__ void zero_kernel() {
    if (threadIdx.x < NEXP) g_cnt[threadIdx.x] = 0;
}

__global__ void gate_kernel(const float* __restrict__ x, const float* __restrict__ gw) {
    int warp = (int)((blockIdx.x * blockDim.x + threadIdx.x) >> 5);
    int lane = threadIdx.x & 31;
    if (warp >= NTOK) return;
    const float4* xr = reinterpret_cast<const float4*>(x + (size_t)warp * DDIM + lane * 16);
    float4 xv[4];
#pragma unroll
    for (int j = 0; j < 4; j++) xv[j] = xr[j];
    float best = -1e30f; int bi = 0;
#pragma unroll
    for (int e = 0; e < NEXP; e++) {
        const float4* gr = reinterpret_cast<const float4*>(gw + (size_t)e * DDIM + lane * 16);
        float s = 0.f;
#pragma unroll
        for (int j = 0; j < 4; j++) {
            float4 g = gr[j];
            s += xv[j].x * g.x + xv[j].y * g.y + xv[j].z * g.z + xv[j].w * g.w;
        }
#pragma unroll
        for (int o = 16; o > 0; o >>= 1) s += __shfl_xor_sync(0xffffffffu, s, o);
        if (s > best) { best = s; bi = e; }
    }
    if (lane == 0) {
        g_expert[warp] = bi;
        g_pos[warp] = atomicAdd(&g_cnt[bi], 1);
    }
}

__global__ void build_tiles_kernel() {
    int off = 0;
    for (int e = 0; e < NEXP; e++) { g_off[e] = off; off += g_cnt[e]; }
    int nt = 0;
    for (int e = 0; e < NEXP; e++) {
        for (int r = 0; r < g_cnt[e]; r += 128) {
            g_tileE[nt] = e;
            g_tileRow[nt] = g_off[e] + r;
            g_tileCnt[nt] = min(128, g_cnt[e] - r);
            nt++;
        }
    }
    g_numTiles = nt;
}

__global__ void scatter_kernel() {
    int t = blockIdx.x * blockDim.x + threadIdx.x;
    if (t >= NTOK) return;
    g_perm[g_off[g_expert[t]] + g_pos[t]] = t;
}

// ===================== fp32 -> (hi, lo) bf16 =====================
__device__ __forceinline__ void split2(float v, __nv_bfloat16& h, __nv_bfloat16& l) {
    h = __float2bfloat16_rn(v);
    l = __float2bfloat16_rn(v - __bfloat162float(h));
}

template<int DST>
__global__ void cvt_kernel(const float* __restrict__ src, int n4) {
    int i = blockIdx.x * blockDim.x + threadIdx.x;
    if (i >= n4) return;
    float4 v = reinterpret_cast<const float4*>(src)[i];
    __nv_bfloat16 h0, h1, h2, h3, l0, l1, l2, l3;
    split2(v.x, h0, l0); split2(v.y, h1, l1); split2(v.z, h2, l2); split2(v.w, h3, l3);
    __nv_bfloat16* hi; __nv_bfloat16* lo;
    if constexpr (DST == 0) { hi = g_xhi;   lo = g_xlo; }
    else if constexpr (DST == 1) { hi = g_sw1hi; lo = g_sw1lo; }
    else if constexpr (DST == 2) { hi = g_sw2hi; lo = g_sw2lo; }
    else if constexpr (DST == 3) { hi = g_w1hi;  lo = g_w1lo; }
    else if constexpr (DST == 4) { hi = g_w3hi;  lo = g_w3lo; }
    else { hi = g_w2hi; lo = g_w2lo; }
    __nv_bfloat162 hA; hA.x = h0; hA.y = h1;
    __nv_bfloat162 hB; hB.x = h2; hB.y = h3;
    __nv_bfloat162 lA; lA.x = l0; lA.y = l1;
    __nv_bfloat162 lB; lB.x = l2; lB.y = l3;
    reinterpret_cast<__nv_bfloat162*>(hi)[i * 2 + 0] = hA;
    reinterpret_cast<__nv_bfloat162*>(hi)[i * 2 + 1] = hB;
    reinterpret_cast<__nv_bfloat162*>(lo)[i * 2 + 0] = lA;
    reinterpret_cast<__nv_bfloat162*>(lo)[i * 2 + 1] = lB;
}

__device__ __forceinline__ float gelu_exact(float v) {
    return 0.5f * v * (1.0f + erff(v * 0.70710678118654752f));
}
__device__ __forceinline__ float silu_f(float v) {
    return v / (1.0f + expf(-v));
}

// ===================== mma.sync GEMM: CTA 128x128, warp 32x64, k-step 32 =====================
// MODE 0: Hs  = gelu(x @ sw1^T)        (hi/lo bf16 out)       KD=512
// MODE 1: A1  = Xg @ w1[e]^T           (fp32 out, sorted pos) KD=512
// MODE 2: Hr  = silu(A1) * (Xg@w3^T)   (hi/lo bf16 out)       KD=512
// MODE 3: out = Hs @ sw2^T             (fp32 write)           KD=2048
// MODE 4: out[perm] += Hr @ w2[e]^T    (fp32 rmw)             KD=2048
template<int MODE>
__global__ __launch_bounds__(256, 1)
void mma_gemm(float* __restrict__ out)
{
    constexpr int KD = (MODE <= 2) ? DDIM : IDIM;
    constexpr int NC = KD / 32;
    constexpr bool ROUTED = (MODE == 1 || MODE == 2 || MODE == 4);

    extern __shared__ __align__(16) char dyns[];
    __shared__ int s_rows[128];

    int bx = blockIdx.x, by = blockIdx.y;
    int rowStart, rowCnt; int eid = 0;
    if constexpr (ROUTED) {
        if (bx >= g_numTiles) return;
        eid = g_tileE[bx]; rowStart = g_tileRow[bx]; rowCnt = g_tileCnt[bx];
    } else {
        rowStart = bx * 128; rowCnt = 128;
    }

    const __nv_bfloat16 *Ahi, *Alo, *Bhi, *Blo;
    size_t bBase;
    if constexpr (MODE == 0) {
        Ahi = g_xhi; Alo = g_xlo; Bhi = g_sw1hi; Blo = g_sw1lo;
        bBase = (size_t)(by * 128) * KD;
    } else if constexpr (MODE == 1) {
        Ahi = g_xhi; Alo = g_xlo; Bhi = g_w1hi; Blo = g_w1lo;
        bBase = (size_t)eid * (IDIM * DDIM) + (size_t)(by * 128) * KD;
    } else if constexpr (MODE == 2) {
        Ahi = g_xhi; Alo = g_xlo; Bhi = g_w3hi; Blo = g_w3lo;
        bBase = (size_t)eid * (IDIM * DDIM) + (size_t)(by * 128) * KD;
    } else if constexpr (MODE == 3) {
        Ahi = g_Hshi; Alo = g_Hslo; Bhi = g_sw2hi; Blo = g_sw2lo;
        bBase = (size_t)(by * 128) * KD;
    } else {
        Ahi = g_Hrhi; Alo = g_Hrlo; Bhi = g_w2hi; Blo = g_w2lo;
        bBase = (size_t)eid * (DDIM * IDIM) + (size_t)(by * 128) * KD;
    }

    int tid = threadIdx.x;
    if (tid < 128) {
        int r = ROUTED ? min(tid, rowCnt - 1) : tid;
        int grow;
        if constexpr (MODE == 1 || MODE == 2) grow = g_perm[rowStart + r];
        else grow = rowStart + r;
        s_rows[tid] = grow;
    }
    __syncthreads();

    uint32_t dynB = smem_u32(dyns);

    // ---- pipeline loads ----
    auto load_stage = [&](int c) {
        int kk = c * 32;
        uint32_t sb = dynB + (uint32_t)((c & 1) * STG);
#pragma unroll
        for (int i = 0; i < 8; i++) {
            int g = i * 256 + tid;
            int arr = g >> 9;            // 0..3
            int idx = g & 511;
            int row = idx >> 2;
            int c8 = (idx & 3) * 8;
            uint32_t dst = sb + (uint32_t)(arr * 10240 + row * (SA * 2) + c8 * 2);
            const __nv_bfloat16* src;
            if (arr == 0)      src = Ahi + (size_t)s_rows[row] * KD + kk + c8;
            else if (arr == 1) src = Alo + (size_t)s_rows[row] * KD + kk + c8;
            else if (arr == 2) src = Bhi + bBase + (size_t)row * KD + kk + c8;
            else               src = Blo + bBase + (size_t)row * KD + kk + c8;
            CP16(dst, src);
        }
        CP_COMMIT();
    };

    int wid = tid >> 5, lane = tid & 31;
    int wm = (wid & 3) * 32;
    int wn = (wid >> 2) * 64;
    int aRow = (lane & 7) + ((lane >> 3) & 1) * 8;   // 0..15
    int aCol = (lane >> 4) * 8;
    int bRow = (lane & 7) + ((lane >> 4) & 1) * 8;
    int bCol = ((lane >> 3) & 1) * 8;

    float acc[2][8][4];
#pragma unroll
    for (int mf = 0; mf < 2; mf++)
#pragma unroll
        for (int nf = 0; nf < 8; nf++)
#pragma unroll
            for (int r = 0; r < 4; r++) acc[mf][nf][r] = 0.f;

    load_stage(0);

    for (int c = 0; c < NC; ++c) {
        if (c + 1 < NC) { load_stage(c + 1); CP_WAIT1(); }
        else            { CP_WAIT0(); }
        __syncthreads();
        uint32_t sb = dynB + (uint32_t)((c & 1) * STG);
#pragma unroll
        for (int kb = 0; kb < 32; kb += 16) {
            uint32_t ah[2][4], al[2][4], bh[8][2], bl[8][2];
#pragma unroll
            for (int mf = 0; mf < 2; mf++) {
                uint32_t off = (uint32_t)(((wm + mf * 16 + aRow) * SA + kb + aCol) * 2);
                LDSM4(ah[mf][0], ah[mf][1], ah[mf][2], ah[mf][3], sb + off);
                LDSM4(al[mf][0], al[mf][1], al[mf][2], al[mf][3], sb + 10240 + off);
            }
#pragma unroll
            for (int n2 = 0; n2 < 4; n2++) {
                uint32_t off = (uint32_t)(((wn + n2 * 16 + bRow) * SA + kb + bCol) * 2);
                uint32_t r0, r1, r2, r3;
                LDSM4(r0, r1, r2, r3, sb + 20480 + off);
                bh[n2 * 2][0] = r0; bh[n2 * 2][1] = r1;
                bh[n2 * 2 + 1][0] = r2; bh[n2 * 2 + 1][1] = r3;
                LDSM4(r0, r1, r2, r3, sb + 30720 + off);
                bl[n2 * 2][0] = r0; bl[n2 * 2][1] = r1;
                bl[n2 * 2 + 1][0] = r2; bl[n2 * 2 + 1][1] = r3;
            }
#pragma unroll
            for (int mf = 0; mf < 2; mf++)
#pragma unroll
                for (int nf = 0; nf < 8; nf++) {
                    MMA(acc[mf][nf], ah[mf], bh[nf]);
                    MMA(acc[mf][nf], ah[mf], bl[nf]);
                    MMA(acc[mf][nf], al[mf], bh[nf]);
                }
        }
        __syncthreads();
    }

    // ---- epilogue ----
#pragma unroll
    for (int mf = 0; mf < 2; mf++) {
#pragma unroll
        for (int half = 0; half < 2; half++) {
            int mloc = wm + mf * 16 + (lane >> 2) + half * 8;
            if (ROUTED && mloc >= rowCnt) continue;
            int sp = rowStart + mloc;
#pragma unroll
            for (int nf = 0; nf < 8; nf++) {
                float v0 = acc[mf][nf][half * 2 + 0];
                float v1 = acc[mf][nf][half * 2 + 1];
                int colg = by * 128 + wn + nf * 8 + (lane & 3) * 2;
                if constexpr (MODE == 0) {
                    float h0 = gelu_exact(v0), h1 = gelu_exact(v1);
                    __nv_bfloat16 a, b, cth, d;
                    split2(h0, a, b); split2(h1, cth, d);
                    __nv_bfloat162 hp; hp.x = a; hp.y = cth;
                    __nv_bfloat162 lp; lp.x = b; lp.y = d;
                    size_t o = (size_t)sp * IDIM + colg;
                    *reinterpret_cast<__nv_bfloat162*>(g_Hshi + o) = hp;
                    *reinterpret_cast<__nv_bfloat162*>(g_Hslo + o) = lp;
                } else if constexpr (MODE == 1) {
                    size_t o = (size_t)sp * IDIM + colg;
                    float2 v; v.x = v0; v.y = v1;
                    *reinterpret_cast<float2*>(g_A1 + o) = v;
                } else if constexpr (MODE == 2) {
                    size_t o = (size_t)sp * IDIM + colg;
                    float2 a1 = *reinterpret_cast<const float2*>(g_A1 + o);
                    float h0 = silu_f(a1.x) * v0, h1 = silu_f(a1.y) * v1;
                    __nv_bfloat16 a, b, cth, d;
                    split2(h0, a, b); split2(h1, cth, d);
                    __nv_bfloat162 hp; hp.x = a; hp.y = cth;
                    __nv_bfloat162 lp; lp.x = b; lp.y = d;
                    *reinterpret_cast<__nv_bfloat162*>(g_Hrhi + o) = hp;
                    *reinterpret_cast<__nv_bfloat162*>(g_Hrlo + o) = lp;
                } else if constexpr (MODE == 3) {
                    size_t o = (size_t)sp * DDIM + colg;
                    float2 v; v.x = v0; v.y = v1;
                    *reinterpret_cast<float2*>(out + o) = v;
                } else { // MODE 4
                    int tok = g_perm[sp];
                    size_t o = (size_t)tok * DDIM + colg;
                    float2 v = *reinterpret_cast<const float2*>(out + o);
                    v.x += v0; v.y += v1;
                    *reinterpret_cast<float2*>(out + o) = v;
                }
            }
        }
    }
}

// ===================== launch =====================
extern "C" void kernel_launch(void* const* d_in, const int* in_sizes, int n_in,
                              void* d_out, int out_size) {
    const float* x   = (const float*)d_in[0];   // [4096, 512]
    const float* gw  = (const float*)d_in[1];   // [8, 512]
    const float* w1  = (const float*)d_in[2];   // [8, 2048, 512]
    const float* w2  = (const float*)d_in[3];   // [8, 512, 2048]
    const float* w3  = (const float*)d_in[4];   // [8, 2048, 512]
    const float* sw1 = (const float*)d_in[5];   // [2048, 512]
    const float* sw2 = (const float*)d_in[6];   // [512, 2048]
    float* out = (float*)d_out;                 // [4096, 512]

    zero_kernel<<<1, 32>>>();
    gate_kernel<<<NTOK / 8, 256>>>(x, gw);
    build_tiles_kernel<<<1, 1>>>();
    scatter_kernel<<<NTOK / 256, 256>>>();

    cvt_kernel<0><<<(NTOK * DDIM) / 4 / 256, 256>>>(x,   (NTOK * DDIM) / 4);
    cvt_kernel<1><<<(IDIM * DDIM) / 4 / 256, 256>>>(sw1, (IDIM * DDIM) / 4);
    cvt_kernel<2><<<(DDIM * IDIM) / 4 / 256, 256>>>(sw2, (DDIM * IDIM) / 4);
    cvt_kernel<3><<<(NEXP * IDIM * DDIM) / 4 / 256, 256>>>(w1, (NEXP * IDIM * DDIM) / 4);
    cvt_kernel<4><<<(NEXP * IDIM * DDIM) / 4 / 256, 256>>>(w3, (NEXP * IDIM * DDIM) / 4);
    cvt_kernel<5><<<(NEXP * DDIM * IDIM) / 4 / 256, 256>>>(w2, (NEXP * DDIM * IDIM) / 4);

    cudaFuncSetAttribute(mma_gemm<0>, cudaFuncAttributeMaxDynamicSharedMemorySize, SMEMSZ);
    cudaFuncSetAttribute(mma_gemm<1>, cudaFuncAttributeMaxDynamicSharedMemorySize, SMEMSZ);
    cudaFuncSetAttribute(mma_gemm<2>, cudaFuncAttributeMaxDynamicSharedMemorySize, SMEMSZ);
    cudaFuncSetAttribute(mma_gemm<3>, cudaFuncAttributeMaxDynamicSharedMemorySize, SMEMSZ);
    cudaFuncSetAttribute(mma_gemm<4>, cudaFuncAttributeMaxDynamicSharedMemorySize, SMEMSZ);

    mma_gemm<0><<<dim3(NTOK / 128, IDIM / 128), 256, SMEMSZ>>>(nullptr);
    mma_gemm<1><<<dim3(MAXTILES, IDIM / 128), 256, SMEMSZ>>>(nullptr);
    mma_gemm<2><<<dim3(MAXTILES, IDIM / 128), 256, SMEMSZ>>>(nullptr);
    mma_gemm<3><<<dim3(NTOK / 128, DDIM / 128), 256, SMEMSZ>>>(out);
    mma_gemm<4><<<dim3(MAXTILES, DDIM / 128), 256, SMEMSZ>>>(out);
}

// round 5
// speedup vs baseline: 3.1927x; 1.2966x over previous
#include <cuda_runtime.h>
#include <cuda_bf16.h>
#include <math.h>
#include <stdint.h>

#define NTOK 4096
#define DDIM 512
#define IDIM 2048
#define NEXP 8
#define MAXTILES 40
#define STGB 36864          // bytes per stage: A 128x32 fp32 @stride36 (18432) + B same
#define SMEMSZ (3 * STGB)   // 110592
#define SROW 36             // smem row stride in floats

// ===================== device scratch =====================
__device__ int g_expert[NTOK];
__device__ int g_pos[NTOK];
__device__ int g_perm[NTOK];
__device__ int g_cnt[NEXP];
__device__ int g_off[NEXP];
__device__ int g_tileE[64];
__device__ int g_tileRow[64];
__device__ int g_tileCnt[64];
__device__ int g_numTiles;

__device__ float g_Hs[(size_t)NTOK * IDIM];
__device__ float g_Hr[(size_t)NTOK * IDIM];
__device__ float g_A1[(size_t)NTOK * IDIM];

// ===================== PTX helpers =====================
__device__ __forceinline__ uint32_t smem_u32(const void* p) {
    uint32_t a;
    asm("{ .reg .u64 t; cvta.to.shared.u64 t, %1; cvt.u32.u64 %0, t; }" : "=r"(a) : "l"(p));
    return a;
}
#define CP16(dst, src) asm volatile("cp.async.cg.shared.global [%0], [%1], 16;" :: "r"(dst), "l"(src))
#define CP_COMMIT()    asm volatile("cp.async.commit_group;" ::: "memory")
#define CP_WAIT2()     asm volatile("cp.async.wait_group 2;" ::: "memory")

__device__ __forceinline__ uint32_t tf32r(float v) {
    uint32_t r;
    asm("cvt.rna.tf32.f32 %0, %1;" : "=r"(r) : "f"(v));
    return r;
}

#define MMAT(d, A, B) \
    asm volatile("mma.sync.aligned.m16n8k8.row.col.f32.tf32.tf32.f32 " \
        "{%0,%1,%2,%3},{%4,%5,%6,%7},{%8,%9},{%0,%1,%2,%3};" \
        : "+f"((d)[0]), "+f"((d)[1]), "+f"((d)[2]), "+f"((d)[3]) \
        : "r"((A)[0]), "r"((A)[1]), "r"((A)[2]), "r"((A)[3]), "r"((B)[0]), "r"((B)[1]))

// ===================== setup kernels =====================
__global__ void zero_kernel() {
    if (threadIdx.x < NEXP) g_cnt[threadIdx.x] = 0;
}

__global__ void gate_kernel(const float* __restrict__ x, const float* __restrict__ gw) {
    int warp = (int)((blockIdx.x * blockDim.x + threadIdx.x) >> 5);
    int lane = threadIdx.x & 31;
    if (warp >= NTOK) return;
    const float4* xr = reinterpret_cast<const float4*>(x + (size_t)warp * DDIM + lane * 16);
    float4 xv[4];
#pragma unroll
    for (int j = 0; j < 4; j++) xv[j] = xr[j];
    float best = -1e30f; int bi = 0;
#pragma unroll
    for (int e = 0; e < NEXP; e++) {
        const float4* gr = reinterpret_cast<const float4*>(gw + (size_t)e * DDIM + lane * 16);
        float s = 0.f;
#pragma unroll
        for (int j = 0; j < 4; j++) {
            float4 g = gr[j];
            s += xv[j].x * g.x + xv[j].y * g.y + xv[j].z * g.z + xv[j].w * g.w;
        }
#pragma unroll
        for (int o = 16; o > 0; o >>= 1) s += __shfl_xor_sync(0xffffffffu, s, o);
        if (s > best) { best = s; bi = e; }
    }
    if (lane == 0) {
        g_expert[warp] = bi;
        g_pos[warp] = atomicAdd(&g_cnt[bi], 1);
    }
}

__global__ void build_tiles_kernel() {
    int off = 0;
    for (int e = 0; e < NEXP; e++) { g_off[e] = off; off += g_cnt[e]; }
    int nt = 0;
    for (int e = 0; e < NEXP; e++) {
        for (int r = 0; r < g_cnt[e]; r += 128) {
            g_tileE[nt] = e;
            g_tileRow[nt] = g_off[e] + r;
            g_tileCnt[nt] = min(128, g_cnt[e] - r);
            nt++;
        }
    }
    g_numTiles = nt;
}

__global__ void scatter_kernel() {
    int t = blockIdx.x * blockDim.x + threadIdx.x;
    if (t >= NTOK) return;
    g_perm[g_off[g_expert[t]] + g_pos[t]] = t;
}

__device__ __forceinline__ float gelu_exact(float v) {
    return 0.5f * v * (1.0f + erff(v * 0.70710678118654752f));
}
__device__ __forceinline__ float silu_f(float v) {
    return v / (1.0f + expf(-v));
}

// ===================== TF32 mma GEMM: CTA 128x128, warp 32x64, k-stage 32 =====================
// MODE 0: Hs  = gelu(x @ sw1^T)        KD=512   A=Aext(x)
// MODE 1: A1  = Xg @ w1[e]^T           KD=512   A=Aext(x), rows via perm
// MODE 2: Hr  = silu(A1)*(Xg @ w3^T)   KD=512   A=Aext(x), rows via perm
// MODE 3: out = Hs @ sw2^T             KD=2048  A=g_Hs (device symbol, selected in-kernel)
// MODE 4: out[perm] += Hr @ w2[e]^T    KD=2048  A=g_Hr (device symbol, selected in-kernel)
template<int MODE>
__global__ __launch_bounds__(256, 1)
void mma_gemm(const float* __restrict__ Aext, const float* __restrict__ Bsrc,
              float* __restrict__ out)
{
    constexpr int KD = (MODE <= 2) ? DDIM : IDIM;
    constexpr int NC = KD / 32;
    constexpr bool ROUTED = (MODE == 1 || MODE == 2 || MODE == 4);

    extern __shared__ __align__(16) char dyns[];
    __shared__ int s_rows[128];

    // device-symbol A sources MUST be resolved in device code (host passes garbage)
    const float* Asrc;
    if constexpr (MODE == 3)      Asrc = g_Hs;
    else if constexpr (MODE == 4) Asrc = g_Hr;
    else                          Asrc = Aext;

    int bx = blockIdx.x, by = blockIdx.y;
    int rowStart, rowCnt; int eid = 0;
    if constexpr (ROUTED) {
        if (bx >= g_numTiles) return;
        eid = g_tileE[bx]; rowStart = g_tileRow[bx]; rowCnt = g_tileCnt[bx];
    } else {
        rowStart = bx * 128; rowCnt = 128;
    }

    size_t bBase;
    if constexpr (MODE == 1 || MODE == 2) bBase = (size_t)eid * (IDIM * DDIM) + (size_t)(by * 128) * KD;
    else if constexpr (MODE == 4)         bBase = (size_t)eid * (DDIM * IDIM) + (size_t)(by * 128) * KD;
    else                                  bBase = (size_t)(by * 128) * KD;

    int tid = threadIdx.x;
    if (tid < 128) {
        int r = ROUTED ? min(tid, rowCnt - 1) : tid;
        int grow;
        if constexpr (MODE == 1 || MODE == 2) grow = g_perm[rowStart + r];
        else grow = rowStart + r;
        s_rows[tid] = grow;
    }
    __syncthreads();

    uint32_t dynB = smem_u32(dyns);

    auto load_stage = [&](int c) {
        if (c < NC) {
            int kk = c * 32;
            uint32_t sb = dynB + (uint32_t)((c % 3) * STGB);
#pragma unroll
            for (int i = 0; i < 8; i++) {
                int g = i * 256 + tid;       // 0..2047
                int isB = g >> 10;
                int idx = g & 1023;
                int row = idx >> 3;
                int c4 = (idx & 7) * 4;
                uint32_t dst = sb + (uint32_t)(isB * 18432 + row * (SROW * 4) + c4 * 4);
                const float* src = isB ? (Bsrc + bBase + (size_t)row * KD + kk + c4)
                                       : (Asrc + (size_t)s_rows[row] * KD + kk + c4);
                CP16(dst, src);
            }
        }
        CP_COMMIT();
    };

    int wid = tid >> 5, lane = tid & 31;
    int gid = lane >> 2, tig = lane & 3;
    int wm = (wid & 3) * 32;
    int wn = (wid >> 2) * 64;

    float acc[2][8][4];
#pragma unroll
    for (int mf = 0; mf < 2; mf++)
#pragma unroll
        for (int nf = 0; nf < 8; nf++)
#pragma unroll
            for (int r = 0; r < 4; r++) acc[mf][nf][r] = 0.f;

    load_stage(0);
    load_stage(1);

    for (int c = 0; c < NC; ++c) {
        load_stage(c + 2);
        CP_WAIT2();
        __syncthreads();
        const float* S = reinterpret_cast<const float*>(dyns + (c % 3) * STGB);
        const float* SB = S + 4608;  // +18432 B
#pragma unroll
        for (int kb = 0; kb < 32; kb += 8) {
            uint32_t af[2][4], bf_[8][2];
#pragma unroll
            for (int mf = 0; mf < 2; mf++) {
                const float* p = S + (size_t)(wm + mf * 16 + gid) * SROW + kb + tig;
                af[mf][0] = tf32r(p[0]);
                af[mf][1] = tf32r(p[8 * SROW]);
                af[mf][2] = tf32r(p[4]);
                af[mf][3] = tf32r(p[8 * SROW + 4]);
            }
#pragma unroll
            for (int nf = 0; nf < 8; nf++) {
                const float* p = SB + (size_t)(wn + nf * 8 + gid) * SROW + kb + tig;
                bf_[nf][0] = tf32r(p[0]);
                bf_[nf][1] = tf32r(p[4]);
            }
#pragma unroll
            for (int mf = 0; mf < 2; mf++)
#pragma unroll
                for (int nf = 0; nf < 8; nf++)
                    MMAT(acc[mf][nf], af[mf], bf_[nf]);
        }
        __syncthreads();
    }

    // ---- epilogue (c-frag: rows gid/gid+8, cols tig*2, tig*2+1) ----
#pragma unroll
    for (int mf = 0; mf < 2; mf++) {
#pragma unroll
        for (int half = 0; half < 2; half++) {
            int mloc = wm + mf * 16 + gid + half * 8;
            if (ROUTED && mloc >= rowCnt) continue;
            int sp = rowStart + mloc;
#pragma unroll
            for (int nf = 0; nf < 8; nf++) {
                float v0 = acc[mf][nf][half * 2 + 0];
                float v1 = acc[mf][nf][half * 2 + 1];
                int colg = by * 128 + wn + nf * 8 + tig * 2;
                if constexpr (MODE == 0) {
                    size_t o = (size_t)sp * IDIM + colg;
                    float2 v; v.x = gelu_exact(v0); v.y = gelu_exact(v1);
                    *reinterpret_cast<float2*>(g_Hs + o) = v;
                } else if constexpr (MODE == 1) {
                    size_t o = (size_t)sp * IDIM + colg;
                    float2 v; v.x = v0; v.y = v1;
                    *reinterpret_cast<float2*>(g_A1 + o) = v;
                } else if constexpr (MODE == 2) {
                    size_t o = (size_t)sp * IDIM + colg;
                    float2 a1 = *reinterpret_cast<const float2*>(g_A1 + o);
                    float2 v; v.x = silu_f(a1.x) * v0; v.y = silu_f(a1.y) * v1;
                    *reinterpret_cast<float2*>(g_Hr + o) = v;
                } else if constexpr (MODE == 3) {
                    size_t o = (size_t)sp * DDIM + colg;
                    float2 v; v.x = v0; v.y = v1;
                    *reinterpret_cast<float2*>(out + o) = v;
                } else {
                    int tok = g_perm[sp];
                    size_t o = (size_t)tok * DDIM + colg;
                    float2 v = *reinterpret_cast<const float2*>(out + o);
                    v.x += v0; v.y += v1;
                    *reinterpret_cast<float2*>(out + o) = v;
                }
            }
        }
    }
}

// ===================== launch =====================
extern "C" void kernel_launch(void* const* d_in, const int* in_sizes, int n_in,
                              void* d_out, int out_size) {
    const float* x   = (const float*)d_in[0];   // [4096, 512]
    const float* gw  = (const float*)d_in[1];   // [8, 512]
    const float* w1  = (const float*)d_in[2];   // [8, 2048, 512]
    const float* w2  = (const float*)d_in[3];   // [8, 512, 2048]
    const float* w3  = (const float*)d_in[4];   // [8, 2048, 512]
    const float* sw1 = (const float*)d_in[5];   // [2048, 512]
    const float* sw2 = (const float*)d_in[6];   // [512, 2048]
    float* out = (float*)d_out;                 // [4096, 512]

    zero_kernel<<<1, 32>>>();
    gate_kernel<<<NTOK / 8, 256>>>(x, gw);
    build_tiles_kernel<<<1, 1>>>();
    scatter_kernel<<<NTOK / 256, 256>>>();

    cudaFuncSetAttribute(mma_gemm<0>, cudaFuncAttributeMaxDynamicSharedMemorySize, SMEMSZ);
    cudaFuncSetAttribute(mma_gemm<1>, cudaFuncAttributeMaxDynamicSharedMemorySize, SMEMSZ);
    cudaFuncSetAttribute(mma_gemm<2>, cudaFuncAttributeMaxDynamicSharedMemorySize, SMEMSZ);
    cudaFuncSetAttribute(mma_gemm<3>, cudaFuncAttributeMaxDynamicSharedMemorySize, SMEMSZ);
    cudaFuncSetAttribute(mma_gemm<4>, cudaFuncAttributeMaxDynamicSharedMemorySize, SMEMSZ);

    mma_gemm<0><<<dim3(NTOK / 128, IDIM / 128), 256, SMEMSZ>>>(x, sw1, nullptr);
    mma_gemm<1><<<dim3(MAXTILES, IDIM / 128), 256, SMEMSZ>>>(x, w1, nullptr);
    mma_gemm<2><<<dim3(MAXTILES, IDIM / 128), 256, SMEMSZ>>>(x, w3, nullptr);
    mma_gemm<3><<<dim3(NTOK / 128, DDIM / 128), 256, SMEMSZ>>>(nullptr, sw2, out);
    mma_gemm<4><<<dim3(MAXTILES, DDIM / 128), 256, SMEMSZ>>>(nullptr, w2, out);
}

// round 6
// speedup vs baseline: 3.4848x; 1.0915x over previous
#include <cuda_runtime.h>
#include <cuda_bf16.h>
#include <math.h>
#include <stdint.h>

#define NTOK 4096
#define DDIM 512
#define IDIM 2048
#define NEXP 8
#define MAXTILES 40
#define SROW 36             // smem row stride in floats

// ===================== device scratch =====================
__device__ int g_expert[NTOK];
__device__ int g_pos[NTOK];
__device__ int g_perm[NTOK];
__device__ int g_cnt[NEXP];
__device__ int g_off[NEXP];
__device__ int g_tileE[64];
__device__ int g_tileRow[64];
__device__ int g_tileCnt[64];
__device__ int g_numTiles;

__device__ float g_Hs[(size_t)NTOK * IDIM];
__device__ float g_Hr[(size_t)NTOK * IDIM];
__device__ float g_A1[(size_t)NTOK * IDIM];

// tf32-pre-rounded copies of all GEMM inputs
__device__ float g_xr[(size_t)NTOK * DDIM];
__device__ float g_sw1r[(size_t)IDIM * DDIM];
__device__ float g_sw2r[(size_t)DDIM * IDIM];
__device__ float g_w1r[(size_t)NEXP * IDIM * DDIM];
__device__ float g_w3r[(size_t)NEXP * IDIM * DDIM];
__device__ float g_w2r[(size_t)NEXP * DDIM * IDIM];

// ===================== PTX helpers =====================
__device__ __forceinline__ uint32_t smem_u32(const void* p) {
    uint32_t a;
    asm("{ .reg .u64 t; cvta.to.shared.u64 t, %1; cvt.u32.u64 %0, t; }" : "=r"(a) : "l"(p));
    return a;
}
#define CP16(dst, src) asm volatile("cp.async.cg.shared.global [%0], [%1], 16;" :: "r"(dst), "l"(src))
#define CP_COMMIT()    asm volatile("cp.async.commit_group;" ::: "memory")
#define CP_WAIT2()     asm volatile("cp.async.wait_group 2;" ::: "memory")

__device__ __forceinline__ uint32_t tf32r(float v) {
    uint32_t r;
    asm("cvt.rna.tf32.f32 %0, %1;" : "=r"(r) : "f"(v));
    return r;
}

#define MMAT(d, A, B) \
    asm volatile("mma.sync.aligned.m16n8k8.row.col.f32.tf32.tf32.f32 " \
        "{%0,%1,%2,%3},{%4,%5,%6,%7},{%8,%9},{%0,%1,%2,%3};" \
        : "+f"((d)[0]), "+f"((d)[1]), "+f"((d)[2]), "+f"((d)[3]) \
        : "r"((A)[0]), "r"((A)[1]), "r"((A)[2]), "r"((A)[3]), "r"((B)[0]), "r"((B)[1]))

// ===================== setup kernels =====================
__global__ void zero_kernel() {
    if (threadIdx.x < NEXP) g_cnt[threadIdx.x] = 0;
}

__global__ void gate_kernel(const float* __restrict__ x, const float* __restrict__ gw) {
    int warp = (int)((blockIdx.x * blockDim.x + threadIdx.x) >> 5);
    int lane = threadIdx.x & 31;
    if (warp >= NTOK) return;
    const float4* xr = reinterpret_cast<const float4*>(x + (size_t)warp * DDIM + lane * 16);
    float4 xv[4];
#pragma unroll
    for (int j = 0; j < 4; j++) xv[j] = xr[j];
    float best = -1e30f; int bi = 0;
#pragma unroll
    for (int e = 0; e < NEXP; e++) {
        const float4* gr = reinterpret_cast<const float4*>(gw + (size_t)e * DDIM + lane * 16);
        float s = 0.f;
#pragma unroll
        for (int j = 0; j < 4; j++) {
            float4 g = gr[j];
            s += xv[j].x * g.x + xv[j].y * g.y + xv[j].z * g.z + xv[j].w * g.w;
        }
#pragma unroll
        for (int o = 16; o > 0; o >>= 1) s += __shfl_xor_sync(0xffffffffu, s, o);
        if (s > best) { best = s; bi = e; }
    }
    if (lane == 0) {
        g_expert[warp] = bi;
        g_pos[warp] = atomicAdd(&g_cnt[bi], 1);
    }
}

__global__ void build_tiles_kernel() {
    int off = 0;
    for (int e = 0; e < NEXP; e++) { g_off[e] = off; off += g_cnt[e]; }
    int nt = 0;
    for (int e = 0; e < NEXP; e++) {
        for (int r = 0; r < g_cnt[e]; r += 128) {
            g_tileE[nt] = e;
            g_tileRow[nt] = g_off[e] + r;
            g_tileCnt[nt] = min(128, g_cnt[e] - r);
            nt++;
        }
    }
    g_numTiles = nt;
}

__global__ void scatter_kernel() {
    int t = blockIdx.x * blockDim.x + threadIdx.x;
    if (t >= NTOK) return;
    g_perm[g_off[g_expert[t]] + g_pos[t]] = t;
}

// ===================== tf32 pre-rounding =====================
// DST: 0=x 1=sw1 2=sw2 3=w1 4=w3 5=w2
template<int DST>
__global__ void round_kernel(const float* __restrict__ src, int n4) {
    int i = blockIdx.x * blockDim.x + threadIdx.x;
    if (i >= n4) return;
    float* dst;
    if constexpr (DST == 0) dst = g_xr;
    else if constexpr (DST == 1) dst = g_sw1r;
    else if constexpr (DST == 2) dst = g_sw2r;
    else if constexpr (DST == 3) dst = g_w1r;
    else if constexpr (DST == 4) dst = g_w3r;
    else dst = g_w2r;
    float4 v = reinterpret_cast<const float4*>(src)[i];
    v.x = __uint_as_float(tf32r(v.x));
    v.y = __uint_as_float(tf32r(v.y));
    v.z = __uint_as_float(tf32r(v.z));
    v.w = __uint_as_float(tf32r(v.w));
    reinterpret_cast<float4*>(dst)[i] = v;
}

__device__ __forceinline__ float gelu_exact(float v) {
    return 0.5f * v * (1.0f + erff(v * 0.70710678118654752f));
}
__device__ __forceinline__ float silu_f(float v) {
    return v / (1.0f + expf(-v));
}

// ===================== TF32 mma GEMM =====================
// MODE 0: Hs  = tf32(gelu(x @ sw1^T))   KD=512   NT=256, 512 thr
// MODE 1: A1  = Xg @ w1[e]^T            KD=512   NT=256, 512 thr (perm rows)
// MODE 2: Hr  = tf32(silu(A1)*Xg@w3^T)  KD=512   NT=256, 512 thr (perm rows)
// MODE 3: out = Hs @ sw2^T              KD=2048  NT=128, 256 thr
// MODE 4: out[perm] += Hr @ w2[e]^T     KD=2048  NT=128, 256 thr
template<int MODE>
__global__ __launch_bounds__((MODE <= 2) ? 512 : 256, 1)
void mma_gemm(float* __restrict__ out)
{
    constexpr int KD = (MODE <= 2) ? DDIM : IDIM;
    constexpr int NC = KD / 32;
    constexpr int NT = (MODE <= 2) ? 256 : 128;
    constexpr int NTHR = (MODE <= 2) ? 512 : 256;
    constexpr bool ROUTED = (MODE == 1 || MODE == 2 || MODE == 4);
    constexpr int A_FL = 128 * SROW;            // 4608 floats
    constexpr int STG_FL = A_FL + NT * SROW;    // stage floats
    constexpr int STG_B = STG_FL * 4;
    constexpr int NV4 = ((128 + NT) * 8) / NTHR;  // cp.async float4s per thread

    extern __shared__ __align__(16) char dyns[];
    __shared__ int s_rows[128];

    const float* Asrc;
    if constexpr (MODE == 3)      Asrc = g_Hs;
    else if constexpr (MODE == 4) Asrc = g_Hr;
    else                          Asrc = g_xr;

    const float* Bsrc;
    if constexpr (MODE == 0)      Bsrc = g_sw1r;
    else if constexpr (MODE == 1) Bsrc = g_w1r;
    else if constexpr (MODE == 2) Bsrc = g_w3r;
    else if constexpr (MODE == 3) Bsrc = g_sw2r;
    else                          Bsrc = g_w2r;

    int bx = blockIdx.x, by = blockIdx.y;
    int rowStart, rowCnt; int eid = 0;
    if constexpr (ROUTED) {
        if (bx >= g_numTiles) return;
        eid = g_tileE[bx]; rowStart = g_tileRow[bx]; rowCnt = g_tileCnt[bx];
    } else {
        rowStart = bx * 128; rowCnt = 128;
    }

    size_t bBase;
    if constexpr (MODE == 1 || MODE == 2) bBase = (size_t)eid * (IDIM * DDIM) + (size_t)(by * NT) * KD;
    else if constexpr (MODE == 4)         bBase = (size_t)eid * (DDIM * IDIM) + (size_t)(by * NT) * KD;
    else                                  bBase = (size_t)(by * NT) * KD;

    int tid = threadIdx.x;
    if (tid < 128) {
        int r = ROUTED ? min(tid, rowCnt - 1) : tid;
        int grow;
        if constexpr (MODE == 1 || MODE == 2) grow = g_perm[rowStart + r];
        else grow = rowStart + r;
        s_rows[tid] = grow;
    }
    __syncthreads();

    uint32_t dynB = smem_u32(dyns);

    auto load_stage = [&](int c) {
        if (c < NC) {
            int kk = c * 32;
            uint32_t sb = dynB + (uint32_t)((c % 3) * STG_B);
#pragma unroll
            for (int i = 0; i < NV4; i++) {
                int g = i * NTHR + tid;
                int isB = (g >= 1024);
                int idx = isB ? (g - 1024) : g;
                int row = idx >> 3;
                int c4 = (idx & 7) * 4;
                uint32_t dst = sb + (uint32_t)(isB * (A_FL * 4) + row * (SROW * 4) + c4 * 4);
                const float* src = isB ? (Bsrc + bBase + (size_t)row * KD + kk + c4)
                                       : (Asrc + (size_t)s_rows[row] * KD + kk + c4);
                CP16(dst, src);
            }
        }
        CP_COMMIT();
    };

    int wid = tid >> 5, lane = tid & 31;
    int gid = lane >> 2, tig = lane & 3;
    int wm = (wid & 3) * 32;
    int wn = (wid >> 2) * 64;

    float acc[2][8][4];
#pragma unroll
    for (int mf = 0; mf < 2; mf++)
#pragma unroll
        for (int nf = 0; nf < 8; nf++)
#pragma unroll
            for (int r = 0; r < 4; r++) acc[mf][nf][r] = 0.f;

    load_stage(0);
    load_stage(1);

    for (int c = 0; c < NC; ++c) {
        load_stage(c + 2);
        CP_WAIT2();
        __syncthreads();
        const uint32_t* S = reinterpret_cast<const uint32_t*>(dyns + (c % 3) * STG_B);
        const uint32_t* SB = S + A_FL;
#pragma unroll
        for (int kb = 0; kb < 32; kb += 8) {
            uint32_t af[2][4], bf_[8][2];
#pragma unroll
            for (int mf = 0; mf < 2; mf++) {
                const uint32_t* p = S + (size_t)(wm + mf * 16 + gid) * SROW + kb + tig;
                af[mf][0] = p[0];
                af[mf][1] = p[8 * SROW];
                af[mf][2] = p[4];
                af[mf][3] = p[8 * SROW + 4];
            }
#pragma unroll
            for (int nf = 0; nf < 8; nf++) {
                const uint32_t* p = SB + (size_t)(wn + nf * 8 + gid) * SROW + kb + tig;
                bf_[nf][0] = p[0];
                bf_[nf][1] = p[4];
            }
#pragma unroll
            for (int mf = 0; mf < 2; mf++)
#pragma unroll
                for (int nf = 0; nf < 8; nf++)
                    MMAT(acc[mf][nf], af[mf], bf_[nf]);
        }
        __syncthreads();
    }

    // ---- epilogue (c-frag: rows gid/gid+8, cols tig*2, tig*2+1) ----
#pragma unroll
    for (int mf = 0; mf < 2; mf++) {
#pragma unroll
        for (int half = 0; half < 2; half++) {
            int mloc = wm + mf * 16 + gid + half * 8;
            if (ROUTED && mloc >= rowCnt) continue;
            int sp = rowStart + mloc;
#pragma unroll
            for (int nf = 0; nf < 8; nf++) {
                float v0 = acc[mf][nf][half * 2 + 0];
                float v1 = acc[mf][nf][half * 2 + 1];
                int colg = by * NT + wn + nf * 8 + tig * 2;
                if constexpr (MODE == 0) {
                    size_t o = (size_t)sp * IDIM + colg;
                    float2 v;
                    v.x = __uint_as_float(tf32r(gelu_exact(v0)));
                    v.y = __uint_as_float(tf32r(gelu_exact(v1)));
                    *reinterpret_cast<float2*>(g_Hs + o) = v;
                } else if constexpr (MODE == 1) {
                    size_t o = (size_t)sp * IDIM + colg;
                    float2 v; v.x = v0; v.y = v1;
                    *reinterpret_cast<float2*>(g_A1 + o) = v;
                } else if constexpr (MODE == 2) {
                    size_t o = (size_t)sp * IDIM + colg;
                    float2 a1 = *reinterpret_cast<const float2*>(g_A1 + o);
                    float2 v;
                    v.x = __uint_as_float(tf32r(silu_f(a1.x) * v0));
                    v.y = __uint_as_float(tf32r(silu_f(a1.y) * v1));
                    *reinterpret_cast<float2*>(g_Hr + o) = v;
                } else if constexpr (MODE == 3) {
                    size_t o = (size_t)sp * DDIM + colg;
                    float2 v; v.x = v0; v.y = v1;
                    *reinterpret_cast<float2*>(out + o) = v;
                } else {
                    int tok = g_perm[sp];
                    size_t o = (size_t)tok * DDIM + colg;
                    float2 v = *reinterpret_cast<const float2*>(out + o);
                    v.x += v0; v.y += v1;
                    *reinterpret_cast<float2*>(out + o) = v;
                }
            }
        }
    }
}

// ===================== launch =====================
extern "C" void kernel_launch(void* const* d_in, const int* in_sizes, int n_in,
                              void* d_out, int out_size) {
    const float* x   = (const float*)d_in[0];   // [4096, 512]
    const float* gw  = (const float*)d_in[1];   // [8, 512]
    const float* w1  = (const float*)d_in[2];   // [8, 2048, 512]
    const float* w2  = (const float*)d_in[3];   // [8, 512, 2048]
    const float* w3  = (const float*)d_in[4];   // [8, 2048, 512]
    const float* sw1 = (const float*)d_in[5];   // [2048, 512]
    const float* sw2 = (const float*)d_in[6];   // [512, 2048]
    float* out = (float*)d_out;                 // [4096, 512]

    zero_kernel<<<1, 32>>>();
    gate_kernel<<<NTOK / 8, 256>>>(x, gw);
    build_tiles_kernel<<<1, 1>>>();
    scatter_kernel<<<NTOK / 256, 256>>>();

    round_kernel<0><<<(NTOK * DDIM) / 4 / 256, 256>>>(x,   (NTOK * DDIM) / 4);
    round_kernel<1><<<(IDIM * DDIM) / 4 / 256, 256>>>(sw1, (IDIM * DDIM) / 4);
    round_kernel<2><<<(DDIM * IDIM) / 4 / 256, 256>>>(sw2, (DDIM * IDIM) / 4);
    round_kernel<3><<<(NEXP * IDIM * DDIM) / 4 / 256, 256>>>(w1, (NEXP * IDIM * DDIM) / 4);
    round_kernel<4><<<(NEXP * IDIM * DDIM) / 4 / 256, 256>>>(w3, (NEXP * IDIM * DDIM) / 4);
    round_kernel<5><<<(NEXP * DDIM * IDIM) / 4 / 256, 256>>>(w2, (NEXP * DDIM * IDIM) / 4);

    constexpr int SM_UP = 3 * (128 + 256) * SROW * 4;   // 165888
    constexpr int SM_DN = 3 * (128 + 128) * SROW * 4;   // 110592
    cudaFuncSetAttribute(mma_gemm<0>, cudaFuncAttributeMaxDynamicSharedMemorySize, SM_UP);
    cudaFuncSetAttribute(mma_gemm<1>, cudaFuncAttributeMaxDynamicSharedMemorySize, SM_UP);
    cudaFuncSetAttribute(mma_gemm<2>, cudaFuncAttributeMaxDynamicSharedMemorySize, SM_UP);
    cudaFuncSetAttribute(mma_gemm<3>, cudaFuncAttributeMaxDynamicSharedMemorySize, SM_DN);
    cudaFuncSetAttribute(mma_gemm<4>, cudaFuncAttributeMaxDynamicSharedMemorySize, SM_DN);

    mma_gemm<0><<<dim3(NTOK / 128, IDIM / 256), 512, SM_UP>>>(nullptr);
    mma_gemm<1><<<dim3(MAXTILES, IDIM / 256), 512, SM_UP>>>(nullptr);
    mma_gemm<2><<<dim3(MAXTILES, IDIM / 256), 512, SM_UP>>>(nullptr);
    mma_gemm<3><<<dim3(NTOK / 128, DDIM / 128), 256, SM_DN>>>(out);
    mma_gemm<4><<<dim3(MAXTILES, DDIM / 128), 256, SM_DN>>>(out);
}